// round 1
// baseline (speedup 1.0000x reference)
#include <cuda_runtime.h>
#include <cuda_bf16.h>

#define NN   30000
#define EE   960000
#define HID  128
#define HH   4
#define DD   32
#define LL   3
#define BB   64

// ---------------- device scratch (no runtime allocation allowed) ----------------
__device__ __align__(16) float  g_h[NN * HID];
__device__ __align__(16) float  g_xl[NN * HID];
__device__ __align__(16) float  g_xr[NN * HID];
__device__ __align__(16) float  g_g[NN * HID];
__device__ int    g_cnt[NN];
__device__ float  g_sumattr[NN * 3];
__device__ int    g_rowptr[NN + 1];
__device__ int    g_fill[NN];
__device__ __align__(16) float4 g_csr[EE];
__device__ __align__(16) float  g_M[LL * 4 * HID];   // per layer: rows {ea0,ea1,ea2,const}
__device__ float  g_bnsum[HID];
__device__ float  g_bnsq[HID];

// ---------------- h = x @ npW + npB ----------------
__global__ void k_node_proj(const float* __restrict__ x,
                            const float* __restrict__ npW,
                            const float* __restrict__ npB)
{
    __shared__ float Ws[28 * HID];
    int tid = threadIdx.x;                    // 128
    for (int i = tid; i < 28 * HID; i += 128) Ws[i] = npW[i];
    __syncthreads();
    float bias = npB[tid];
    int row0 = blockIdx.x * 32;
    for (int r = 0; r < 32; r++) {
        int row = row0 + r;
        if (row >= NN) break;
        const float* xr = x + row * 28;
        float acc = bias;
        #pragma unroll
        for (int k = 0; k < 28; k++) acc = fmaf(__ldg(xr + k), Ws[k * HID + tid], acc);
        g_h[row * HID + tid] = acc;
    }
}

// ---------------- M[l] = epW @ We[l],  c[l] = epB @ We[l] ----------------
__global__ void k_precM(const float* __restrict__ epW,
                        const float* __restrict__ epB,
                        const float* __restrict__ We)
{
    int c = threadIdx.x;                      // 128
    for (int l = 0; l < LL; l++) {
        const float* W = We + l * HID * HID;
        float m0 = 0.f, m1 = 0.f, m2 = 0.f, mc = 0.f;
        for (int k = 0; k < HID; k++) {
            float w = W[k * HID + c];
            m0 = fmaf(epW[0 * HID + k], w, m0);
            m1 = fmaf(epW[1 * HID + k], w, m1);
            m2 = fmaf(epW[2 * HID + k], w, m2);
            mc = fmaf(epB[k], w, mc);
        }
        g_M[l * 512 + 0 * HID + c] = m0;
        g_M[l * 512 + 1 * HID + c] = m1;
        g_M[l * 512 + 2 * HID + c] = m2;
        g_M[l * 512 + 3 * HID + c] = mc;
    }
}

// ---------------- degree + edge_attr segment sums ----------------
__global__ void k_deg(const int* __restrict__ ei, const float* __restrict__ ea)
{
    int e = blockIdx.x * blockDim.x + threadIdx.x;
    if (e >= EE) return;
    int d = ei[EE + e];
    atomicAdd(&g_cnt[d], 1);
    atomicAdd(&g_sumattr[d * 3 + 0], ea[e * 3 + 0]);
    atomicAdd(&g_sumattr[d * 3 + 1], ea[e * 3 + 1]);
    atomicAdd(&g_sumattr[d * 3 + 2], ea[e * 3 + 2]);
}

// ---------------- exclusive prefix scan of degrees (single block) ----------------
__global__ void k_scan()
{
    __shared__ int part[1024];
    int t = threadIdx.x;
    int begin = t * 30; if (begin > NN) begin = NN;
    int end = begin + 30; if (end > NN) end = NN;
    int s = 0;
    for (int i = begin; i < end; i++) s += g_cnt[i];
    part[t] = s;
    __syncthreads();
    for (int off = 1; off < 1024; off <<= 1) {
        int v = (t >= off) ? part[t - off] : 0;
        __syncthreads();
        part[t] += v;
        __syncthreads();
    }
    int run = (t == 0) ? 0 : part[t - 1];
    for (int i = begin; i < end; i++) { g_rowptr[i] = run; run += g_cnt[i]; }
    if (t == 1023) g_rowptr[NN] = part[1023];
}

// ---------------- scatter edges into CSR (packed src + edge_attr) ----------------
__global__ void k_scatter(const int* __restrict__ ei, const float* __restrict__ ea)
{
    int e = blockIdx.x * blockDim.x + threadIdx.x;
    if (e >= EE) return;
    int s = ei[e];
    int d = ei[EE + e];
    int pos = g_rowptr[d] + atomicAdd(&g_fill[d], 1);
    g_csr[pos] = make_float4(__int_as_float(s), ea[e * 3 + 0], ea[e * 3 + 1], ea[e * 3 + 2]);
}

// ---------------- xl = h@Wl+bl, xr = h@Wr+br (blockIdx.z selects) ----------------
__global__ void __launch_bounds__(128)
k_gemm(const float* __restrict__ W0, const float* __restrict__ b0,
       const float* __restrict__ W1, const float* __restrict__ b1)
{
    __shared__ __align__(16) float hs[64][64];
    __shared__ __align__(16) float Ws[64][HID];
    const float* W  = blockIdx.z ? W1 : W0;
    const float* bv = blockIdx.z ? b1 : b0;
    float* out = blockIdx.z ? g_xr : g_xl;

    int tid = threadIdx.x;                    // 128
    int tx = tid & 15;                        // 16 col groups * 8 cols
    int ty = tid >> 4;                        // 8 row groups * 8 rows
    int row0 = blockIdx.x * 64;

    float acc[8][8];
    {
        float4 c0 = *(const float4*)&bv[tx * 8];
        float4 c1 = *(const float4*)&bv[tx * 8 + 4];
        #pragma unroll
        for (int i = 0; i < 8; i++) {
            acc[i][0] = c0.x; acc[i][1] = c0.y; acc[i][2] = c0.z; acc[i][3] = c0.w;
            acc[i][4] = c1.x; acc[i][5] = c1.y; acc[i][6] = c1.z; acc[i][7] = c1.w;
        }
    }

    for (int kb = 0; kb < HID; kb += 64) {
        for (int t = tid; t < 1024; t += 128) {        // 64x64 = 1024 float4
            int r = t >> 4;
            int kk = (t & 15) << 2;
            int row = row0 + r; if (row >= NN) row = NN - 1;
            *(float4*)&hs[r][kk] = *(const float4*)&g_h[row * HID + kb + kk];
        }
        for (int t = tid; t < 2048; t += 128) {        // 64x128 = 2048 float4
            int kr = t >> 5;
            int c4 = (t & 31) << 2;
            *(float4*)&Ws[kr][c4] = *(const float4*)&W[(kb + kr) * HID + c4];
        }
        __syncthreads();
        #pragma unroll 4
        for (int k = 0; k < 64; k++) {
            float a[8];
            #pragma unroll
            for (int i = 0; i < 8; i++) a[i] = hs[ty * 8 + i][k];
            float4 bq0 = *(const float4*)&Ws[k][tx * 8];
            float4 bq1 = *(const float4*)&Ws[k][tx * 8 + 4];
            #pragma unroll
            for (int i = 0; i < 8; i++) {
                acc[i][0] = fmaf(a[i], bq0.x, acc[i][0]);
                acc[i][1] = fmaf(a[i], bq0.y, acc[i][1]);
                acc[i][2] = fmaf(a[i], bq0.z, acc[i][2]);
                acc[i][3] = fmaf(a[i], bq0.w, acc[i][3]);
                acc[i][4] = fmaf(a[i], bq1.x, acc[i][4]);
                acc[i][5] = fmaf(a[i], bq1.y, acc[i][5]);
                acc[i][6] = fmaf(a[i], bq1.z, acc[i][6]);
                acc[i][7] = fmaf(a[i], bq1.w, acc[i][7]);
            }
        }
        __syncthreads();
    }
    #pragma unroll
    for (int i = 0; i < 8; i++) {
        int row = row0 + ty * 8 + i;
        if (row < NN) {
            float4 o0 = make_float4(acc[i][0], acc[i][1], acc[i][2], acc[i][3]);
            float4 o1 = make_float4(acc[i][4], acc[i][5], acc[i][6], acc[i][7]);
            *(float4*)&out[row * HID + tx * 8] = o0;
            *(float4*)&out[row * HID + tx * 8 + 4] = o1;
        }
    }
}

// ---------------- GATv2 layer: one warp per dst node, online softmax ----------------
__global__ void __launch_bounds__(256)
k_gat(const float* __restrict__ att, const float* __restrict__ gbias, int layer)
{
    int warp = threadIdx.x >> 5;
    int lane = threadIdx.x & 31;
    int v = blockIdx.x * 8 + warp;
    if (v >= NN) return;

    const float* Mb = g_M + layer * 512;
    float4 M0 = *(const float4*)(Mb + 0 * HID + lane * 4);
    float4 M1 = *(const float4*)(Mb + 1 * HID + lane * 4);
    float4 M2 = *(const float4*)(Mb + 2 * HID + lane * 4);
    float4 MC = *(const float4*)(Mb + 3 * HID + lane * 4);
    float4 av = *(const float4*)(att + layer * HID + lane * 4);
    float4 xr4 = *(const float4*)(g_xr + (size_t)v * HID + lane * 4);

    float mx = -1e30f;
    float den = 0.f;
    float4 acc = make_float4(0.f, 0.f, 0.f, 0.f);

    auto upd = [&](float a0, float a1, float a2, float aC, float4 xs) {
        float t0 = xs.x + xr4.x + fmaf(a0, M0.x, fmaf(a1, M1.x, fmaf(a2, M2.x, aC * MC.x)));
        float t1 = xs.y + xr4.y + fmaf(a0, M0.y, fmaf(a1, M1.y, fmaf(a2, M2.y, aC * MC.y)));
        float t2 = xs.z + xr4.z + fmaf(a0, M0.z, fmaf(a1, M1.z, fmaf(a2, M2.z, aC * MC.z)));
        float t3 = xs.w + xr4.w + fmaf(a0, M0.w, fmaf(a1, M1.w, fmaf(a2, M2.w, aC * MC.w)));
        t0 = fmaxf(t0, 0.2f * t0);
        t1 = fmaxf(t1, 0.2f * t1);
        t2 = fmaxf(t2, 0.2f * t2);
        t3 = fmaxf(t3, 0.2f * t3);
        float p = fmaf(t0, av.x, fmaf(t1, av.y, fmaf(t2, av.z, t3 * av.w)));
        p += __shfl_xor_sync(0xffffffffu, p, 1);
        p += __shfl_xor_sync(0xffffffffu, p, 2);
        p += __shfl_xor_sync(0xffffffffu, p, 4);     // per-head (8-lane) sum
        float nm = fmaxf(mx, p);
        float sc = __expf(mx - nm);
        float f  = __expf(p - nm);
        den = fmaf(den, sc, f);
        acc.x = fmaf(acc.x, sc, f * xs.x);
        acc.y = fmaf(acc.y, sc, f * xs.y);
        acc.z = fmaf(acc.z, sc, f * xs.z);
        acc.w = fmaf(acc.w, sc, f * xs.w);
        mx = nm;
    };

    int e0 = g_rowptr[v], e1 = g_rowptr[v + 1];
    for (int e = e0; e < e1; e++) {
        float4 ed = __ldg(&g_csr[e]);
        int s = __float_as_int(ed.x);
        float4 xs = *(const float4*)(g_xl + (size_t)s * HID + lane * 4);
        upd(ed.y, ed.z, ed.w, 1.0f, xs);
    }
    // self loop: edge feature = mean of incoming projected edge feats
    {
        float cv = (float)g_cnt[v];
        float rc = 1.0f / fmaxf(cv, 1.0f);
        float a0 = g_sumattr[v * 3 + 0] * rc;
        float a1 = g_sumattr[v * 3 + 1] * rc;
        float a2 = g_sumattr[v * 3 + 2] * rc;
        float aC = (cv > 0.f) ? 1.0f : 0.0f;
        float4 xs = *(const float4*)(g_xl + (size_t)v * HID + lane * 4);
        upd(a0, a1, a2, aC, xs);
    }
    float inv = 1.0f / (den + 1e-16f);
    float4 gb = *(const float4*)(gbias + layer * HID + lane * 4);
    float4 o = make_float4(acc.x * inv + gb.x, acc.y * inv + gb.y,
                           acc.z * inv + gb.z, acc.w * inv + gb.w);
    *(float4*)(g_g + (size_t)v * HID + lane * 4) = o;
}

// ---------------- batchnorm stats over nodes ----------------
__global__ void k_bnstats()
{
    int c = threadIdx.x;                      // 128
    float s = 0.f, s2 = 0.f;
    for (int v = blockIdx.x; v < NN; v += gridDim.x) {
        float val = g_g[(size_t)v * HID + c];
        s += val;
        s2 = fmaf(val, val, s2);
    }
    atomicAdd(&g_bnsum[c], s);
    atomicAdd(&g_bnsq[c], s2);
}

// ---------------- h = relu(bn(g)) + h ----------------
__global__ void k_bnapply(const float* __restrict__ bng, const float* __restrict__ bnb, int layer)
{
    int idx = blockIdx.x * blockDim.x + threadIdx.x;
    if (idx >= NN * HID) return;
    int c = idx & (HID - 1);
    const float invN = 1.0f / NN;
    float mean = g_bnsum[c] * invN;
    float var  = g_bnsq[c] * invN - mean * mean;
    float rstd = rsqrtf(var + 1e-5f);
    float gam = bng[layer * HID + c], bet = bnb[layer * HID + c];
    float val = (g_g[idx] - mean) * rstd * gam + bet;
    g_h[idx] += fmaxf(val, 0.f);
}

// ---------------- MLP head (single block) ----------------
__global__ void __launch_bounds__(1024)
k_head(const int* __restrict__ mut, const float* __restrict__ pert,
       const float* __restrict__ r1W, const float* __restrict__ r1b,
       const float* __restrict__ bn1g, const float* __restrict__ bn1b,
       const float* __restrict__ r2W, const float* __restrict__ r2b,
       const float* __restrict__ bn2g, const float* __restrict__ bn2b,
       const float* __restrict__ r3W, const float* __restrict__ r3b,
       const float* __restrict__ clsW, const float* __restrict__ clsb,
       const float* __restrict__ regW, const float* __restrict__ regb,
       float* __restrict__ out)
{
    extern __shared__ float sm[];
    float* comb = sm;                 // 64 * 138
    float* z1 = comb + 64 * 138;      // 64 * 257
    float* z2 = z1 + 64 * 257;        // 64 * 129
    float* z3 = z2 + 64 * 129;        // 64 * 65
    int tid = threadIdx.x;            // 1024

    for (int i = tid; i < 64 * 137; i += 1024) {
        int b = i / 137, k = i % 137;
        float v = (k < HID) ? g_h[(size_t)mut[b] * HID + k] : pert[b * 9 + (k - HID)];
        comb[b * 138 + k] = v;
    }
    __syncthreads();
    for (int i = tid; i < 64 * 256; i += 1024) {
        int b = i >> 8, c = i & 255;
        float acc = r1b[c];
        for (int k = 0; k < 137; k++) acc = fmaf(comb[b * 138 + k], r1W[k * 256 + c], acc);
        z1[b * 257 + c] = acc;
    }
    __syncthreads();
    if (tid < 256) {
        int c = tid;
        float s = 0.f, s2 = 0.f;
        for (int b = 0; b < 64; b++) { float v = z1[b * 257 + c]; s += v; s2 = fmaf(v, v, s2); }
        float m = s * (1.f / 64), var = s2 * (1.f / 64) - m * m;
        float rs = rsqrtf(var + 1e-5f);
        float gm = bn1g[c], bt = bn1b[c];
        for (int b = 0; b < 64; b++)
            z1[b * 257 + c] = fmaxf((z1[b * 257 + c] - m) * rs * gm + bt, 0.f);
    }
    __syncthreads();
    for (int i = tid; i < 64 * 128; i += 1024) {
        int b = i >> 7, c = i & 127;
        float acc = r2b[c];
        for (int k = 0; k < 256; k++) acc = fmaf(z1[b * 257 + k], r2W[k * 128 + c], acc);
        z2[b * 129 + c] = acc;
    }
    __syncthreads();
    if (tid < 128) {
        int c = tid;
        float s = 0.f, s2 = 0.f;
        for (int b = 0; b < 64; b++) { float v = z2[b * 129 + c]; s += v; s2 = fmaf(v, v, s2); }
        float m = s * (1.f / 64), var = s2 * (1.f / 64) - m * m;
        float rs = rsqrtf(var + 1e-5f);
        float gm = bn2g[c], bt = bn2b[c];
        for (int b = 0; b < 64; b++)
            z2[b * 129 + c] = fmaxf((z2[b * 129 + c] - m) * rs * gm + bt, 0.f);
    }
    __syncthreads();
    for (int i = tid; i < 64 * 64; i += 1024) {
        int b = i >> 6, c = i & 63;
        float acc = r3b[c];
        for (int k = 0; k < 128; k++) acc = fmaf(z2[b * 129 + k], r3W[k * 64 + c], acc);
        z3[b * 65 + c] = fmaxf(acc, 0.f);
    }
    __syncthreads();
    if (tid < 64) {
        int b = tid;
        float c1 = clsb[0], c2 = regb[0];
        for (int k = 0; k < 64; k++) {
            float v = z3[b * 65 + k];
            c1 = fmaf(v, clsW[k], c1);
            c2 = fmaf(v, regW[k], c2);
        }
        out[b * 2 + 0] = c1;
        out[b * 2 + 1] = c2;
    }
}

// ---------------- launch ----------------
extern "C" void kernel_launch(void* const* d_in, const int* in_sizes, int n_in,
                              void* d_out, int out_size)
{
    (void)in_sizes; (void)n_in; (void)out_size;
    const float* x     = (const float*)d_in[0];
    const float* eattr = (const float*)d_in[1];
    const int*   eidx  = (const int*)d_in[2];
    const int*   mut   = (const int*)d_in[3];
    const float* pert  = (const float*)d_in[4];
    const float* npW   = (const float*)d_in[5];
    const float* npB   = (const float*)d_in[6];
    const float* epW   = (const float*)d_in[7];
    const float* epB   = (const float*)d_in[8];
    const float* Wl    = (const float*)d_in[9];
    const float* bl    = (const float*)d_in[10];
    const float* Wr    = (const float*)d_in[11];
    const float* br    = (const float*)d_in[12];
    const float* We    = (const float*)d_in[13];
    const float* att   = (const float*)d_in[14];
    const float* gbias = (const float*)d_in[15];
    const float* bng   = (const float*)d_in[16];
    const float* bnb   = (const float*)d_in[17];
    const float* r1W   = (const float*)d_in[18];
    const float* r1b   = (const float*)d_in[19];
    const float* bn1g  = (const float*)d_in[20];
    const float* bn1b  = (const float*)d_in[21];
    const float* r2W   = (const float*)d_in[22];
    const float* r2b   = (const float*)d_in[23];
    const float* bn2g  = (const float*)d_in[24];
    const float* bn2b  = (const float*)d_in[25];
    const float* r3W   = (const float*)d_in[26];
    const float* r3b   = (const float*)d_in[27];
    const float* clsW  = (const float*)d_in[28];
    const float* clsb  = (const float*)d_in[29];
    const float* regW  = (const float*)d_in[30];
    const float* regb  = (const float*)d_in[31];
    float* out = (float*)d_out;

    void *p_cnt, *p_sum, *p_fill, *p_bnsum, *p_bnsq;
    cudaGetSymbolAddress(&p_cnt, g_cnt);
    cudaGetSymbolAddress(&p_sum, g_sumattr);
    cudaGetSymbolAddress(&p_fill, g_fill);
    cudaGetSymbolAddress(&p_bnsum, g_bnsum);
    cudaGetSymbolAddress(&p_bnsq, g_bnsq);

    cudaMemsetAsync(p_cnt, 0, NN * sizeof(int));
    cudaMemsetAsync(p_sum, 0, NN * 3 * sizeof(float));
    cudaMemsetAsync(p_fill, 0, NN * sizeof(int));

    k_node_proj<<<(NN + 31) / 32, 128>>>(x, npW, npB);
    k_precM<<<1, 128>>>(epW, epB, We);
    k_deg<<<(EE + 255) / 256, 256>>>(eidx, eattr);
    k_scan<<<1, 1024>>>();
    k_scatter<<<(EE + 255) / 256, 256>>>(eidx, eattr);

    for (int l = 0; l < LL; l++) {
        k_gemm<<<dim3((NN + 63) / 64, 1, 2), 128>>>(
            Wl + (size_t)l * HID * HID, bl + l * HID,
            Wr + (size_t)l * HID * HID, br + l * HID);
        k_gat<<<(NN + 7) / 8, 256>>>(att, gbias, l);
        cudaMemsetAsync(p_bnsum, 0, HID * sizeof(float));
        cudaMemsetAsync(p_bnsq, 0, HID * sizeof(float));
        k_bnstats<<<240, 128>>>();
        k_bnapply<<<(NN * HID + 255) / 256, 256>>>(bng, bnb, l);
    }

    size_t head_smem = (64 * 138 + 64 * 257 + 64 * 129 + 64 * 65) * sizeof(float);
    cudaFuncSetAttribute(k_head, cudaFuncAttributeMaxDynamicSharedMemorySize, (int)head_smem);
    k_head<<<1, 1024, head_smem>>>(mut, pert, r1W, r1b, bn1g, bn1b,
                                   r2W, r2b, bn2g, bn2b, r3W, r3b,
                                   clsW, clsb, regW, regb, out);
}

// round 2
// speedup vs baseline: 1.1764x; 1.1764x over previous
#include <cuda_runtime.h>
#include <cuda_bf16.h>

#define NN   30000
#define EE   960000
#define HID  128
#define LL   3
#define BB   64

// ---------------- device scratch ----------------
__device__ __align__(16) float  g_h[NN * HID];
__device__ __align__(16) float  g_xl[NN * HID];
__device__ __align__(16) float  g_xr[NN * HID];
__device__ __align__(16) float  g_g[NN * HID];
__device__ __align__(16) int    g_cnt[32768];          // padded for int4 scan
__device__ int    g_rowptr[NN + 1];
__device__ int    g_fill[NN];
__device__ __align__(16) float4 g_csr[EE];
__device__ __align__(16) float  g_M[LL * 4 * HID];     // {ea0,ea1,ea2,const} per layer
__device__ float  g_bnsum[HID];
__device__ float  g_bnsq[HID];
__device__ __align__(16) float  g_z1[BB * 256];
__device__ __align__(16) float  g_z2[BB * 128];

// ---------------- h = x @ npW + npB ----------------
__global__ void k_node_proj(const float* __restrict__ x,
                            const float* __restrict__ npW,
                            const float* __restrict__ npB)
{
    __shared__ float Ws[28 * HID];
    int tid = threadIdx.x;                    // 128
    for (int i = tid; i < 28 * HID; i += 128) Ws[i] = npW[i];
    __syncthreads();
    float bias = npB[tid];
    int row0 = blockIdx.x * 32;
    for (int r = 0; r < 32; r++) {
        int row = row0 + r;
        if (row >= NN) break;
        const float* xr = x + row * 28;
        float acc = bias;
        #pragma unroll
        for (int k = 0; k < 28; k++) acc = fmaf(__ldg(xr + k), Ws[k * HID + tid], acc);
        g_h[row * HID + tid] = acc;
    }
}

// ---------------- M[l] = epW @ We[l], const row = epB @ We[l] ----------------
__global__ void k_precM(const float* __restrict__ epW,
                        const float* __restrict__ epB,
                        const float* __restrict__ We)
{
    int c = threadIdx.x;                      // 128
    for (int l = 0; l < LL; l++) {
        const float* W = We + l * HID * HID;
        float m0 = 0.f, m1 = 0.f, m2 = 0.f, mc = 0.f;
        for (int k = 0; k < HID; k++) {
            float w = W[k * HID + c];
            m0 = fmaf(epW[0 * HID + k], w, m0);
            m1 = fmaf(epW[1 * HID + k], w, m1);
            m2 = fmaf(epW[2 * HID + k], w, m2);
            mc = fmaf(epB[k], w, mc);
        }
        g_M[l * 512 + 0 * HID + c] = m0;
        g_M[l * 512 + 1 * HID + c] = m1;
        g_M[l * 512 + 2 * HID + c] = m2;
        g_M[l * 512 + 3 * HID + c] = mc;
    }
}

// ---------------- degree histogram ----------------
__global__ void k_deg(const int* __restrict__ ei)
{
    int e = blockIdx.x * blockDim.x + threadIdx.x;
    if (e >= EE) return;
    atomicAdd(&g_cnt[ei[EE + e]], 1);
}

// ---------------- exclusive scan (single block, int4) ----------------
__global__ void k_scan()
{
    __shared__ int part[1024];
    int t = threadIdx.x;
    int base = t * 32;                         // 32768 total, padding is zero
    int vals[32];
    const int4* c4 = (const int4*)&g_cnt[base];
    int s = 0;
    #pragma unroll
    for (int q = 0; q < 8; q++) {
        int4 v = c4[q];
        vals[q * 4 + 0] = v.x; vals[q * 4 + 1] = v.y;
        vals[q * 4 + 2] = v.z; vals[q * 4 + 3] = v.w;
        s += v.x + v.y + v.z + v.w;
    }
    part[t] = s;
    __syncthreads();
    for (int off = 1; off < 1024; off <<= 1) {
        int v = (t >= off) ? part[t - off] : 0;
        __syncthreads();
        part[t] += v;
        __syncthreads();
    }
    int run = (t == 0) ? 0 : part[t - 1];
    #pragma unroll
    for (int q = 0; q < 32; q++) {
        int i = base + q;
        if (i <= NN) g_rowptr[i] = run;
        run += vals[q];
    }
}

// ---------------- scatter edges into CSR ----------------
__global__ void k_scatter(const int* __restrict__ ei, const float* __restrict__ ea)
{
    int e = blockIdx.x * blockDim.x + threadIdx.x;
    if (e >= EE) return;
    int s = ei[e];
    int d = ei[EE + e];
    int pos = g_rowptr[d] + atomicAdd(&g_fill[d], 1);
    g_csr[pos] = make_float4(__int_as_float(s), ea[e * 3 + 0], ea[e * 3 + 1], ea[e * 3 + 2]);
}

// ---------------- xl/xr GEMM: 128x128 tile, 256 threads ----------------
__global__ void __launch_bounds__(256)
k_gemm(const float* __restrict__ W0, const float* __restrict__ b0,
       const float* __restrict__ W1, const float* __restrict__ b1)
{
    __shared__ __align__(16) float As[32][132];   // k-major, transposed A
    __shared__ __align__(16) float Bs[32][132];
    const float* W  = blockIdx.z ? W1 : W0;
    const float* bv = blockIdx.z ? b1 : b0;
    float* out = blockIdx.z ? g_xr : g_xl;

    int tid = threadIdx.x;
    int tx = tid & 15;                        // col group
    int ty = tid >> 4;                        // row group
    int row0 = blockIdx.x * 128;

    float acc[8][8];
    {
        float4 c0 = *(const float4*)&bv[tx * 4];
        float4 c1 = *(const float4*)&bv[64 + tx * 4];
        #pragma unroll
        for (int i = 0; i < 8; i++) {
            acc[i][0] = c0.x; acc[i][1] = c0.y; acc[i][2] = c0.z; acc[i][3] = c0.w;
            acc[i][4] = c1.x; acc[i][5] = c1.y; acc[i][6] = c1.z; acc[i][7] = c1.w;
        }
    }

    for (int kb = 0; kb < HID; kb += 32) {
        #pragma unroll
        for (int q = 0; q < 4; q++) {          // A: 128 rows x 32 k
            int idx = tid + q * 256;           // 1024 float4
            int r = idx >> 3;
            int kk = (idx & 7) << 2;
            int row = row0 + r; if (row >= NN) row = NN - 1;
            float4 v = *(const float4*)&g_h[row * HID + kb + kk];
            As[kk + 0][r] = v.x; As[kk + 1][r] = v.y;
            As[kk + 2][r] = v.z; As[kk + 3][r] = v.w;
        }
        #pragma unroll
        for (int q = 0; q < 4; q++) {          // B: 32 k x 128 col
            int idx = tid + q * 256;
            int kk = idx >> 5;
            int c = (idx & 31) << 2;
            *(float4*)&Bs[kk][c] = *(const float4*)&W[(kb + kk) * HID + c];
        }
        __syncthreads();
        #pragma unroll
        for (int k = 0; k < 32; k++) {
            float4 a0 = *(const float4*)&As[k][ty * 4];
            float4 a1 = *(const float4*)&As[k][64 + ty * 4];
            float4 bq0 = *(const float4*)&Bs[k][tx * 4];
            float4 bq1 = *(const float4*)&Bs[k][64 + tx * 4];
            float a[8] = {a0.x, a0.y, a0.z, a0.w, a1.x, a1.y, a1.z, a1.w};
            float b[8] = {bq0.x, bq0.y, bq0.z, bq0.w, bq1.x, bq1.y, bq1.z, bq1.w};
            #pragma unroll
            for (int i = 0; i < 8; i++)
                #pragma unroll
                for (int j = 0; j < 8; j++)
                    acc[i][j] = fmaf(a[i], b[j], acc[i][j]);
        }
        __syncthreads();
    }
    #pragma unroll
    for (int i = 0; i < 8; i++) {
        int row = row0 + ((i < 4) ? (ty * 4 + i) : (64 + ty * 4 + i - 4));
        if (row < NN) {
            *(float4*)&out[row * HID + tx * 4] =
                make_float4(acc[i][0], acc[i][1], acc[i][2], acc[i][3]);
            *(float4*)&out[row * HID + 64 + tx * 4] =
                make_float4(acc[i][4], acc[i][5], acc[i][6], acc[i][7]);
        }
    }
}

// ---------------- GATv2: one warp per dst, no-max softmax ----------------
__global__ void __launch_bounds__(256)
k_gat(const float* __restrict__ att, const float* __restrict__ gbias, int layer)
{
    int warp = threadIdx.x >> 5;
    int lane = threadIdx.x & 31;
    int v = blockIdx.x * 8 + warp;
    if (v >= NN) return;

    const float* Mb = g_M + layer * 512;
    float4 M0 = *(const float4*)(Mb + 0 * HID + lane * 4);
    float4 M1 = *(const float4*)(Mb + 1 * HID + lane * 4);
    float4 M2 = *(const float4*)(Mb + 2 * HID + lane * 4);
    float4 MC = *(const float4*)(Mb + 3 * HID + lane * 4);
    float4 av = *(const float4*)(att + layer * HID + lane * 4);
    float4 xr4 = *(const float4*)(g_xr + (size_t)v * HID + lane * 4);
    float4 base = make_float4(xr4.x + MC.x, xr4.y + MC.y, xr4.z + MC.z, xr4.w + MC.w);

    float den = 0.f;
    float4 acc = make_float4(0.f, 0.f, 0.f, 0.f);
    float sa0 = 0.f, sa1 = 0.f, sa2 = 0.f;

    int e0 = g_rowptr[v], e1 = g_rowptr[v + 1];
    float4 ed = make_float4(0.f, 0.f, 0.f, 0.f);
    float4 xs = make_float4(0.f, 0.f, 0.f, 0.f);
    if (e0 < e1) {
        ed = __ldg(&g_csr[e0]);
        xs = *(const float4*)(g_xl + (size_t)__float_as_int(ed.x) * HID + lane * 4);
    }
    for (int e = e0; e < e1; e++) {
        float4 edc = ed;
        float4 xsc = xs;
        if (e + 1 < e1) {
            ed = __ldg(&g_csr[e + 1]);
            xs = *(const float4*)(g_xl + (size_t)__float_as_int(ed.x) * HID + lane * 4);
        }
        sa0 += edc.y; sa1 += edc.z; sa2 += edc.w;
        float t0 = xsc.x + fmaf(edc.y, M0.x, fmaf(edc.z, M1.x, fmaf(edc.w, M2.x, base.x)));
        float t1 = xsc.y + fmaf(edc.y, M0.y, fmaf(edc.z, M1.y, fmaf(edc.w, M2.y, base.y)));
        float t2 = xsc.z + fmaf(edc.y, M0.z, fmaf(edc.z, M1.z, fmaf(edc.w, M2.z, base.z)));
        float t3 = xsc.w + fmaf(edc.y, M0.w, fmaf(edc.z, M1.w, fmaf(edc.w, M2.w, base.w)));
        t0 = fmaxf(t0, 0.2f * t0);
        t1 = fmaxf(t1, 0.2f * t1);
        t2 = fmaxf(t2, 0.2f * t2);
        t3 = fmaxf(t3, 0.2f * t3);
        float p = fmaf(t0, av.x, fmaf(t1, av.y, fmaf(t2, av.z, t3 * av.w)));
        p += __shfl_xor_sync(0xffffffffu, p, 1);
        p += __shfl_xor_sync(0xffffffffu, p, 2);
        p += __shfl_xor_sync(0xffffffffu, p, 4);      // per-head sum (8 lanes)
        float f = __expf(p);
        den += f;
        acc.x = fmaf(f, xsc.x, acc.x);
        acc.y = fmaf(f, xsc.y, acc.y);
        acc.z = fmaf(f, xsc.z, acc.z);
        acc.w = fmaf(f, xsc.w, acc.w);
    }
    // self loop (edge feature = mean of incoming projected attrs)
    {
        int cnt = e1 - e0;
        float rc = 1.0f / fmaxf((float)cnt, 1.0f);
        float a0 = sa0 * rc, a1 = sa1 * rc, a2 = sa2 * rc;
        float aCm1 = (cnt > 0) ? 0.0f : -1.0f;        // aC - 1
        float4 xv = *(const float4*)(g_xl + (size_t)v * HID + lane * 4);
        float t0 = xv.x + fmaf(a0, M0.x, fmaf(a1, M1.x, fmaf(a2, M2.x, fmaf(aCm1, MC.x, base.x))));
        float t1 = xv.y + fmaf(a0, M0.y, fmaf(a1, M1.y, fmaf(a2, M2.y, fmaf(aCm1, MC.y, base.y))));
        float t2 = xv.z + fmaf(a0, M0.z, fmaf(a1, M1.z, fmaf(a2, M2.z, fmaf(aCm1, MC.z, base.z))));
        float t3 = xv.w + fmaf(a0, M0.w, fmaf(a1, M1.w, fmaf(a2, M2.w, fmaf(aCm1, MC.w, base.w))));
        t0 = fmaxf(t0, 0.2f * t0);
        t1 = fmaxf(t1, 0.2f * t1);
        t2 = fmaxf(t2, 0.2f * t2);
        t3 = fmaxf(t3, 0.2f * t3);
        float p = fmaf(t0, av.x, fmaf(t1, av.y, fmaf(t2, av.z, t3 * av.w)));
        p += __shfl_xor_sync(0xffffffffu, p, 1);
        p += __shfl_xor_sync(0xffffffffu, p, 2);
        p += __shfl_xor_sync(0xffffffffu, p, 4);
        float f = __expf(p);
        den += f;
        acc.x = fmaf(f, xv.x, acc.x);
        acc.y = fmaf(f, xv.y, acc.y);
        acc.z = fmaf(f, xv.z, acc.z);
        acc.w = fmaf(f, xv.w, acc.w);
    }
    float inv = 1.0f / (den + 1e-16f);
    float4 gb = *(const float4*)(gbias + layer * HID + lane * 4);
    *(float4*)(g_g + (size_t)v * HID + lane * 4) =
        make_float4(fmaf(acc.x, inv, gb.x), fmaf(acc.y, inv, gb.y),
                    fmaf(acc.z, inv, gb.z), fmaf(acc.w, inv, gb.w));
}

// ---------------- batchnorm stats ----------------
__global__ void k_bnstats()
{
    int c = threadIdx.x;                      // 128
    float s = 0.f, s2 = 0.f;
    for (int v = blockIdx.x; v < NN; v += gridDim.x) {
        float val = g_g[(size_t)v * HID + c];
        s += val;
        s2 = fmaf(val, val, s2);
    }
    atomicAdd(&g_bnsum[c], s);
    atomicAdd(&g_bnsq[c], s2);
}

// ---------------- h = relu(bn(g)) + h (float4) ----------------
__global__ void k_bnapply(const float* __restrict__ bng, const float* __restrict__ bnb, int layer)
{
    int idx = blockIdx.x * blockDim.x + threadIdx.x;   // over NN*HID/4
    if (idx >= NN * HID / 4) return;
    int cg = (idx & 31) * 4;
    const float invN = 1.0f / NN;
    float4 sum = *(const float4*)&g_bnsum[cg];
    float4 sq  = *(const float4*)&g_bnsq[cg];
    float4 gm  = *(const float4*)&bng[layer * HID + cg];
    float4 bt  = *(const float4*)&bnb[layer * HID + cg];
    float m0 = sum.x * invN, m1 = sum.y * invN, m2 = sum.z * invN, m3 = sum.w * invN;
    float r0 = rsqrtf(sq.x * invN - m0 * m0 + 1e-5f) * gm.x;
    float r1 = rsqrtf(sq.y * invN - m1 * m1 + 1e-5f) * gm.y;
    float r2 = rsqrtf(sq.z * invN - m2 * m2 + 1e-5f) * gm.z;
    float r3 = rsqrtf(sq.w * invN - m3 * m3 + 1e-5f) * gm.w;
    float4 g4 = *(const float4*)&g_g[idx * 4];
    float4 h4 = *(const float4*)&g_h[idx * 4];
    h4.x += fmaxf(fmaf(g4.x - m0, r0, bt.x), 0.f);
    h4.y += fmaxf(fmaf(g4.y - m1, r1, bt.y), 0.f);
    h4.z += fmaxf(fmaf(g4.z - m2, r2, bt.z), 0.f);
    h4.w += fmaxf(fmaf(g4.w - m3, r3, bt.w), 0.f);
    *(float4*)&g_h[idx * 4] = h4;
}

// ---------------- head: z1 = comb @ r1W + r1b (grid 16 x 256thr) ----------------
__global__ void __launch_bounds__(256)
k_head1(const int* __restrict__ mut, const float* __restrict__ pert,
        const float* __restrict__ r1W, const float* __restrict__ r1b)
{
    __shared__ float comb[64 * 140];
    __shared__ float Ws[137 * 16];
    int tid = threadIdx.x;
    int colbase = blockIdx.x * 16;
    for (int i = tid; i < 64 * 137; i += 256) {
        int b = i / 137, k = i - b * 137;
        float vv = (k < HID) ? g_h[(size_t)mut[b] * HID + k] : pert[b * 9 + (k - HID)];
        comb[b * 140 + k] = vv;
    }
    for (int i = tid; i < 137 * 16; i += 256) {
        int k = i >> 4, c = i & 15;
        Ws[k * 16 + c] = r1W[k * 256 + colbase + c];
    }
    __syncthreads();
    int row = tid >> 2;
    int cq = (tid & 3) * 4;
    float4 accv = *(const float4*)&r1b[colbase + cq];
    for (int k = 0; k < 137; k++) {
        float a = comb[row * 140 + k];
        float4 w = *(const float4*)&Ws[k * 16 + cq];
        accv.x = fmaf(a, w.x, accv.x);
        accv.y = fmaf(a, w.y, accv.y);
        accv.z = fmaf(a, w.z, accv.z);
        accv.w = fmaf(a, w.w, accv.w);
    }
    *(float4*)&g_z1[row * 256 + colbase + cq] = accv;
}

// ---------------- head BN+relu over 64 rows ----------------
__global__ void k_bnrelu_head(float* __restrict__ z, const float* __restrict__ g,
                              const float* __restrict__ b, int cols)
{
    int c = threadIdx.x;
    if (c >= cols) return;
    float s = 0.f, s2 = 0.f;
    for (int r = 0; r < 64; r++) {
        float v = z[r * cols + c];
        s += v; s2 = fmaf(v, v, s2);
    }
    float m = s * (1.f / 64), var = s2 * (1.f / 64) - m * m;
    float rs = rsqrtf(var + 1e-5f) * g[c];
    float bt = b[c];
    for (int r = 0; r < 64; r++)
        z[r * cols + c] = fmaxf(fmaf(z[r * cols + c] - m, rs, bt), 0.f);
}

// ---------------- head: z2 = z1 @ r2W + r2b (grid 8 x 256thr, dyn smem) ----------------
__global__ void __launch_bounds__(256)
k_head2(const float* __restrict__ r2W, const float* __restrict__ r2b)
{
    extern __shared__ float sm[];
    float* z1s = sm;                  // 64 * 260
    float* Ws  = sm + 64 * 260;       // 256 * 16
    int tid = threadIdx.x;
    int colbase = blockIdx.x * 16;
    for (int i = tid; i < 64 * 64; i += 256) {     // 4096 float4 = 64*256 floats
        int r = i >> 6;
        int kq = (i & 63) * 4;
        *(float4*)&z1s[r * 260 + kq] = *(const float4*)&g_z1[r * 256 + kq];
    }
    for (int i = tid; i < 256 * 16; i += 256) {
        int k = i >> 4, c = i & 15;
        Ws[k * 16 + c] = r2W[k * 128 + colbase + c];
    }
    __syncthreads();
    int row = tid >> 2;
    int cq = (tid & 3) * 4;
    float4 accv = *(const float4*)&r2b[colbase + cq];
    for (int k = 0; k < 256; k++) {
        float a = z1s[row * 260 + k];
        float4 w = *(const float4*)&Ws[k * 16 + cq];
        accv.x = fmaf(a, w.x, accv.x);
        accv.y = fmaf(a, w.y, accv.y);
        accv.z = fmaf(a, w.z, accv.z);
        accv.w = fmaf(a, w.w, accv.w);
    }
    *(float4*)&g_z2[row * 128 + colbase + cq] = accv;
}

// ---------------- head: z3 = relu(z2 @ r3W + r3b); outputs (1 block, dyn smem) ----------------
__global__ void __launch_bounds__(256)
k_head3(const float* __restrict__ r3W, const float* __restrict__ r3b,
        const float* __restrict__ clsW, const float* __restrict__ clsb,
        const float* __restrict__ regW, const float* __restrict__ regb,
        float* __restrict__ out)
{
    extern __shared__ float sm[];
    float* z2s = sm;                  // 64 * 132
    float* Ws  = sm + 64 * 132;       // 128 * 64
    float* z3  = Ws + 128 * 64;       // 64 * 68
    int tid = threadIdx.x;
    for (int i = tid; i < 64 * 32; i += 256) {     // 64*128 floats as float4
        int r = i >> 5;
        int kq = (i & 31) * 4;
        *(float4*)&z2s[r * 132 + kq] = *(const float4*)&g_z2[r * 128 + kq];
    }
    for (int i = tid; i < 128 * 16; i += 256) {    // 8192 floats as float4
        int idx4 = i * 4;
        *(float4*)&Ws[idx4] = *(const float4*)&r3W[idx4];
    }
    __syncthreads();
    int row = tid >> 2;
    int cg = (tid & 3) * 16;
    float acc[16];
    #pragma unroll
    for (int j = 0; j < 16; j++) acc[j] = r3b[cg + j];
    for (int k = 0; k < 128; k++) {
        float a = z2s[row * 132 + k];
        #pragma unroll
        for (int j = 0; j < 16; j++)
            acc[j] = fmaf(a, Ws[k * 64 + cg + j], acc[j]);
    }
    #pragma unroll
    for (int j = 0; j < 16; j++) z3[row * 68 + cg + j] = fmaxf(acc[j], 0.f);
    __syncthreads();
    if (tid < 64) {
        int b = tid;
        float c1 = clsb[0], c2 = regb[0];
        for (int k = 0; k < 64; k++) {
            float v = z3[b * 68 + k];
            c1 = fmaf(v, clsW[k], c1);
            c2 = fmaf(v, regW[k], c2);
        }
        out[b * 2 + 0] = c1;
        out[b * 2 + 1] = c2;
    }
}

// ---------------- launch ----------------
extern "C" void kernel_launch(void* const* d_in, const int* in_sizes, int n_in,
                              void* d_out, int out_size)
{
    (void)in_sizes; (void)n_in; (void)out_size;
    const float* x     = (const float*)d_in[0];
    const float* eattr = (const float*)d_in[1];
    const int*   eidx  = (const int*)d_in[2];
    const int*   mut   = (const int*)d_in[3];
    const float* pert  = (const float*)d_in[4];
    const float* npW   = (const float*)d_in[5];
    const float* npB   = (const float*)d_in[6];
    const float* epW   = (const float*)d_in[7];
    const float* epB   = (const float*)d_in[8];
    const float* Wl    = (const float*)d_in[9];
    const float* bl    = (const float*)d_in[10];
    const float* Wr    = (const float*)d_in[11];
    const float* br    = (const float*)d_in[12];
    const float* We    = (const float*)d_in[13];
    const float* att   = (const float*)d_in[14];
    const float* gbias = (const float*)d_in[15];
    const float* bng   = (const float*)d_in[16];
    const float* bnb   = (const float*)d_in[17];
    const float* r1W   = (const float*)d_in[18];
    const float* r1b   = (const float*)d_in[19];
    const float* bn1g  = (const float*)d_in[20];
    const float* bn1b  = (const float*)d_in[21];
    const float* r2W   = (const float*)d_in[22];
    const float* r2b   = (const float*)d_in[23];
    const float* bn2g  = (const float*)d_in[24];
    const float* bn2b  = (const float*)d_in[25];
    const float* r3W   = (const float*)d_in[26];
    const float* r3b   = (const float*)d_in[27];
    const float* clsW  = (const float*)d_in[28];
    const float* clsb  = (const float*)d_in[29];
    const float* regW  = (const float*)d_in[30];
    const float* regb  = (const float*)d_in[31];
    float* out = (float*)d_out;

    void *p_cnt, *p_fill, *p_bnsum, *p_bnsq, *p_z1, *p_z2;
    cudaGetSymbolAddress(&p_cnt, g_cnt);
    cudaGetSymbolAddress(&p_fill, g_fill);
    cudaGetSymbolAddress(&p_bnsum, g_bnsum);
    cudaGetSymbolAddress(&p_bnsq, g_bnsq);
    cudaGetSymbolAddress(&p_z1, g_z1);
    cudaGetSymbolAddress(&p_z2, g_z2);

    cudaMemsetAsync(p_cnt, 0, 32768 * sizeof(int));
    cudaMemsetAsync(p_fill, 0, NN * sizeof(int));

    k_node_proj<<<(NN + 31) / 32, 128>>>(x, npW, npB);
    k_precM<<<1, 128>>>(epW, epB, We);
    k_deg<<<(EE + 255) / 256, 256>>>(eidx);
    k_scan<<<1, 1024>>>();
    k_scatter<<<(EE + 255) / 256, 256>>>(eidx, eattr);

    for (int l = 0; l < LL; l++) {
        k_gemm<<<dim3((NN + 127) / 128, 1, 2), 256>>>(
            Wl + (size_t)l * HID * HID, bl + l * HID,
            Wr + (size_t)l * HID * HID, br + l * HID);
        k_gat<<<(NN + 7) / 8, 256>>>(att, gbias, l);
        cudaMemsetAsync(p_bnsum, 0, HID * sizeof(float));
        cudaMemsetAsync(p_bnsq, 0, HID * sizeof(float));
        k_bnstats<<<240, 128>>>();
        k_bnapply<<<(NN * HID / 4 + 255) / 256, 256>>>(bng, bnb, l);
    }

    k_head1<<<16, 256>>>(mut, pert, r1W, r1b);
    k_bnrelu_head<<<1, 256>>>((float*)p_z1, bn1g, bn1b, 256);
    size_t smem2 = (64 * 260 + 256 * 16) * sizeof(float);
    cudaFuncSetAttribute(k_head2, cudaFuncAttributeMaxDynamicSharedMemorySize, (int)smem2);
    k_head2<<<8, 256, smem2>>>(r2W, r2b);
    k_bnrelu_head<<<1, 128>>>((float*)p_z2, bn2g, bn2b, 128);
    size_t smem3 = (64 * 132 + 128 * 64 + 64 * 68) * sizeof(float);
    cudaFuncSetAttribute(k_head3, cudaFuncAttributeMaxDynamicSharedMemorySize, (int)smem3);
    k_head3<<<1, 256, smem3>>>(r3W, r3b, clsW, clsb, regW, regb, out);
}